// round 7
// baseline (speedup 1.0000x reference)
#include <cuda_runtime.h>
#include <cuda_bf16.h>
#include <cstdint>

#define NEG 1000000000000.0f
#define WSCALE 32.0f
#define INV_WSCALE (1.0f / 32.0f)

// Pre-pass outputs.
__device__ uint8_t  g_A8[8192 * 1024];    // A e4m3 [8192][1024], 8 MB
__device__ uint8_t  g_W8T[1536 * 1024];   // (32*W)^T e4m3 [1536][1024], 1.5 MB
// Q/K after projection + RoPE: [bh][l][64] bf16 (bf16x2 words).
__device__ uint32_t g_Qh[192 * 512 * 32];
__device__ uint32_t g_Kh[192 * 512 * 32];

// ---------------------------------------------------------------------------
// helpers
// ---------------------------------------------------------------------------
__device__ __forceinline__ uint32_t pack_bf16x2(float lo, float hi) {
    uint32_t r;
    asm("cvt.rn.bf16x2.f32 %0, %1, %2;" : "=r"(r) : "f"(hi), "f"(lo));
    return r;
}

// pack 4 floats -> 4 e4m3 bytes (ascending byte order = v0..v3)
__device__ __forceinline__ uint32_t pack_e4m3x4(float v0, float v1, float v2, float v3) {
    uint32_t r;
    asm("{\n\t.reg .b16 l, h;\n\t"
        "cvt.rn.satfinite.e4m3x2.f32 l, %2, %1;\n\t"
        "cvt.rn.satfinite.e4m3x2.f32 h, %4, %3;\n\t"
        "mov.b32 %0, {l, h};\n\t}"
        : "=r"(r) : "f"(v0), "f"(v1), "f"(v2), "f"(v3));
    return r;
}

__device__ __forceinline__ uint32_t smem_u32(const void* p) {
    return (uint32_t)__cvta_generic_to_shared(p);
}

__device__ __forceinline__ void cp16(uint32_t dst, const void* src) {
    asm volatile("cp.async.cg.shared.global [%0], [%1], 16;" :: "r"(dst), "l"(src));
}
#define CP_COMMIT() asm volatile("cp.async.commit_group;" ::: "memory")
#define CP_WAIT1()  asm volatile("cp.async.wait_group 1;" ::: "memory")

#define SWZ128(x) ((x) ^ (((x) >> 3) & 0x70))

__device__ __forceinline__ void ldsm_x4(uint32_t& r0, uint32_t& r1,
                                        uint32_t& r2, uint32_t& r3, uint32_t addr) {
    asm volatile("ldmatrix.sync.aligned.m8n8.x4.shared.b16 {%0,%1,%2,%3}, [%4];"
                 : "=r"(r0), "=r"(r1), "=r"(r2), "=r"(r3) : "r"(addr));
}

// fp8 e4m3 mma: D[16x8] += A[16x32] * B[32x8]
__device__ __forceinline__ void mma_fp8(float* c, const uint32_t* a, const uint32_t* b) {
    asm volatile(
        "mma.sync.aligned.m16n8k32.row.col.f32.e4m3.e4m3.f32 "
        "{%0,%1,%2,%3}, {%4,%5,%6,%7}, {%8,%9}, {%0,%1,%2,%3};"
        : "+f"(c[0]), "+f"(c[1]), "+f"(c[2]), "+f"(c[3])
        : "r"(a[0]), "r"(a[1]), "r"(a[2]), "r"(a[3]), "r"(b[0]), "r"(b[1]));
}

// bf16 mma for kernel 2
__device__ __forceinline__ void mma_bf16(float* c, const uint32_t* a, const uint32_t* b) {
    asm volatile(
        "mma.sync.aligned.m16n8k16.row.col.f32.bf16.bf16.f32 "
        "{%0,%1,%2,%3}, {%4,%5,%6,%7}, {%8,%9}, {%0,%1,%2,%3};"
        : "+f"(c[0]), "+f"(c[1]), "+f"(c[2]), "+f"(c[3])
        : "r"(a[0]), "r"(a[1]), "r"(a[2]), "r"(a[3]), "r"(b[0]), "r"(b[1]));
}

// ---------------------------------------------------------------------------
// Pre-pass 1: A fp32 -> e4m3. One thread: 8 floats -> 8 bytes.
// ---------------------------------------------------------------------------
__global__ __launch_bounds__(256) void convertA8_kernel(const float* __restrict__ A) {
    size_t i = (size_t)blockIdx.x * 256 + threadIdx.x;   // < 8192*1024/8
    const float4* p = (const float4*)A + i * 2;
    float4 v0 = p[0], v1 = p[1];
    uint2 u;
    u.x = pack_e4m3x4(v0.x, v0.y, v0.z, v0.w);
    u.y = pack_e4m3x4(v1.x, v1.y, v1.z, v1.w);
    ((uint2*)g_A8)[i] = u;
}

// ---------------------------------------------------------------------------
// Pre-pass 2: W[1024,1536] fp32 -> (32*W)^T [1536,1024] e4m3 (tiled transpose).
// Block: 32 n-cols x 64 k-rows.
// ---------------------------------------------------------------------------
__global__ __launch_bounds__(256) void wtrans8_kernel(const float* __restrict__ W) {
    __shared__ float s[64][33];
    const int tid = threadIdx.x;
    const int n0 = blockIdx.x * 32;
    const int k0 = blockIdx.y * 64;
#pragma unroll
    for (int r = 0; r < 8; ++r) {
        int idx = tid + r * 256;
        int kr = idx >> 5, nc = idx & 31;
        s[kr][nc] = W[(size_t)(k0 + kr) * 1536 + n0 + nc] * WSCALE;
    }
    __syncthreads();
    // each thread: one n-row, 8 k-values -> 8 bytes
    int n = tid >> 3;            // 0..31
    int kc = (tid & 7) * 8;      // 0..56
    uint2 u;
    u.x = pack_e4m3x4(s[kc + 0][n], s[kc + 1][n], s[kc + 2][n], s[kc + 3][n]);
    u.y = pack_e4m3x4(s[kc + 4][n], s[kc + 5][n], s[kc + 6][n], s[kc + 7][n]);
    *(uint2*)&g_W8T[(size_t)(n0 + n) * 1024 + k0 + kc] = u;
}

// ---------------------------------------------------------------------------
// Kernel 1: C[8192,1536] = A @ W + b via fp8 mma.sync (fp32 acc), fused RoPE.
// CTA: 128x128 tile (one head), BK=128 bytes, 3-stage cp.async, 256 threads
// (8 warps, 2(m) x 4(n); warp tile 64x32).
// ---------------------------------------------------------------------------
#define STG8 32768                    // A 16KB + B 16KB per stage
#define K1_SMEM (3 * STG8)

__global__ __launch_bounds__(256) void proj_rope_fp8(
    const float* __restrict__ bias,   // [1536]
    const float* __restrict__ pe)     // [512,64]
{
    extern __shared__ __align__(1024) char smem[];
    const uint32_t db = smem_u32(smem);

    const int tid = threadIdx.x;
    const int lane = tid & 31;
    const int wid = tid >> 5;
    const int warp_m = wid >> 2;      // 0..1
    const int warp_n = wid & 3;       // 0..3
    const int h  = blockIdx.x;        // head 0..11
    const int bn = h * 128;
    const int bm = blockIdx.y * 128;

    float acc[4][4][4] = {};

    // ldmatrix lane addressing (bytes within tile)
    const int a_row_l = warp_m * 64 + (lane & 15);        // + mt*16
    const int a_kb_l  = (lane & 16);                      // 0 or 16 bytes
    const int b_row_l = warp_n * 32 + (lane & 7) + ((lane >> 4) << 3);  // + np*16
    const int b_kb_l  = (lane & 8) << 1;                  // 0 or 16 bytes

    auto issue_load = [&](int s, int k0) {
        const uint32_t ab = db + s * STG8;
#pragma unroll
        for (int r = 0; r < 4; ++r) {
            int idx = tid + r * 256;
            int row = idx >> 3, c = idx & 7;
            cp16(ab + SWZ128(row * 128 + c * 16),
                 g_A8 + (size_t)(bm + row) * 1024 + k0 + c * 16);
        }
        const uint32_t bb = ab + 16384;
#pragma unroll
        for (int r = 0; r < 4; ++r) {
            int idx = tid + r * 256;
            int row = idx >> 3, c = idx & 7;
            cp16(bb + SWZ128(row * 128 + c * 16),
                 g_W8T + (size_t)(bn + row) * 1024 + k0 + c * 16);
        }
        CP_COMMIT();
    };

    issue_load(0, 0);
    issue_load(1, 128);

    for (int it = 0; it < 8; ++it) {
        const int s = it - (it / 3) * 3;        // it % 3
        CP_WAIT1();
        __syncthreads();
        if (it + 2 < 8) {
            int s2 = (it + 2) - ((it + 2) / 3) * 3;
            issue_load(s2, (it + 2) * 128);
        } else {
            CP_COMMIT();
        }

        const uint32_t As_b = db + s * STG8;
        const uint32_t Bs_b = As_b + 16384;

#pragma unroll
        for (int ks = 0; ks < 4; ++ks) {        // 4 ksteps of 32 bytes
            const int kb = ks * 32;
            uint32_t af[4][4];
#pragma unroll
            for (int mt = 0; mt < 4; ++mt) {
                uint32_t addr = As_b + SWZ128((a_row_l + mt * 16) * 128 + kb + a_kb_l);
                ldsm_x4(af[mt][0], af[mt][1], af[mt][2], af[mt][3], addr);
            }
            uint32_t bf[4][2];
#pragma unroll
            for (int np = 0; np < 2; ++np) {
                uint32_t addr = Bs_b + SWZ128((b_row_l + np * 16) * 128 + kb + b_kb_l);
                ldsm_x4(bf[2 * np][0], bf[2 * np][1],
                        bf[2 * np + 1][0], bf[2 * np + 1][1], addr);
            }
#pragma unroll
            for (int mt = 0; mt < 4; ++mt)
#pragma unroll
                for (int nt = 0; nt < 4; ++nt)
                    mma_fp8(acc[mt][nt], af[mt], bf[nt]);
        }
        __syncthreads();
    }

    // ---- epilogue: 1/32 scale + bias + RoPE -> bf16 Q/K
    const int g = lane >> 2, t = lane & 3;
    const int cb = warp_n * 32;               // 0,32,64,96 within head
    const bool isK = (cb >= 64);
    uint32_t* dst = isK ? g_Kh : g_Qh;

    float be[4], bo[4];
    int pi[4];
#pragma unroll
    for (int nt = 0; nt < 4; ++nt) {
        int c = cb + nt * 8 + 2 * t;          // even col within head
        be[nt] = bias[bn + c];
        bo[nt] = bias[bn + c + 1];
        pi[nt] = (c & 63) >> 1;               // RoPE pair index 0..31
    }

    const float2* pe2 = (const float2*)pe;

#pragma unroll
    for (int mt = 0; mt < 4; ++mt) {
#pragma unroll
        for (int rr = 0; rr < 2; ++rr) {
            int m = bm + warp_m * 64 + mt * 16 + g + 8 * rr;
            int l = m & 511;
            int b = m >> 9;
            size_t rowb = ((size_t)(b * 12 + h) * 512 + l) * 32;
#pragma unroll
            for (int nt = 0; nt < 4; ++nt) {
                float2 sc = pe2[l * 32 + pi[nt]];   // x=sin, y=cos
                float e = acc[mt][nt][2 * rr]     * INV_WSCALE + be[nt];
                float o = acc[mt][nt][2 * rr + 1] * INV_WSCALE + bo[nt];
                float re = e * sc.y - o * sc.x;
                float ro = o * sc.y + e * sc.x;
                dst[rowb + pi[nt]] = pack_bf16x2(re, ro);
            }
        }
    }
}

// ---------------------------------------------------------------------------
// Kernel 2: per (b,h): logits = Q @ K^T (bf16 mma.sync), fused mask/tril/scale.
// ---------------------------------------------------------------------------
#define PQ 72

__device__ __forceinline__ void ldsm_x4b(uint32_t& r0, uint32_t& r1,
                                         uint32_t& r2, uint32_t& r3, uint32_t addr) {
    asm volatile("ldmatrix.sync.aligned.m8n8.x4.shared.b16 {%0,%1,%2,%3}, [%4];"
                 : "=r"(r0), "=r"(r1), "=r"(r2), "=r"(r3) : "r"(addr));
}

__global__ __launch_bounds__(256) void qk_logits_kernel(
    const int* __restrict__ mask,   // [16,512]
    float* __restrict__ out)        // [16,12,512,512]
{
    __shared__ __align__(16) uint16_t Qs[128 * PQ];
    __shared__ __align__(16) uint16_t Ks[128 * PQ];

    const int tid = threadIdx.x;
    const int lane = tid & 31;
    const int wid = tid >> 5;
    const int warp_m = wid >> 2;
    const int warp_n = wid & 3;
    const int bh = blockIdx.z;
    const int b  = bh / 12;
    const int bm = blockIdx.y * 128;
    const int bn = blockIdx.x * 128;

    const uint4* Qg = (const uint4*)(g_Qh + ((size_t)bh * 512 + bm) * 32);
    const uint4* Kg = (const uint4*)(g_Kh + ((size_t)bh * 512 + bn) * 32);
#pragma unroll
    for (int r = 0; r < 4; ++r) {
        int chunk = tid + r * 256;
        int row = chunk >> 3;
        int kg  = chunk & 7;
        *(uint4*)&Qs[row * PQ + kg * 8] = Qg[row * 8 + kg];
        *(uint4*)&Ks[row * PQ + kg * 8] = Kg[row * 8 + kg];
    }
    __syncthreads();

    const uint32_t Qs_b = smem_u32(Qs);
    const uint32_t Ks_b = smem_u32(Ks);

    const int a_row_l = warp_m * 64 + (lane & 15);
    const int a_col_l = (lane & 16) ? 8 : 0;
    const int b_row_l = warp_n * 32 + (lane & 7) + ((lane & 16) >> 1);
    const int b_col_l = (lane & 8) ? 8 : 0;

    float acc[4][4][4] = {};

#pragma unroll
    for (int ks = 0; ks < 4; ++ks) {
        int k = ks * 16;
        uint32_t af[4][4];
#pragma unroll
        for (int mt = 0; mt < 4; ++mt) {
            uint32_t addr = Qs_b + ((a_row_l + mt * 16) * PQ + k + a_col_l) * 2;
            ldsm_x4b(af[mt][0], af[mt][1], af[mt][2], af[mt][3], addr);
        }
        uint32_t bf[4][2];
#pragma unroll
        for (int np = 0; np < 2; ++np) {
            uint32_t addr = Ks_b + ((b_row_l + np * 16) * PQ + k + b_col_l) * 2;
            ldsm_x4b(bf[2 * np][0], bf[2 * np][1],
                     bf[2 * np + 1][0], bf[2 * np + 1][1], addr);
        }
#pragma unroll
        for (int mt = 0; mt < 4; ++mt)
#pragma unroll
            for (int nt = 0; nt < 4; ++nt)
                mma_bf16(acc[mt][nt], af[mt], bf[nt]);
    }

    const int g = lane >> 2, t = lane & 3;
    const int* mb = mask + b * 512;
    float mv0[4], mv1[4];
    int ncol[4];
#pragma unroll
    for (int nt = 0; nt < 4; ++nt) {
        int n = bn + warp_n * 32 + nt * 8 + 2 * t;
        ncol[nt] = n;
        mv0[nt] = (float)mb[n];
        mv1[nt] = (float)mb[n + 1];
    }

#pragma unroll
    for (int mt = 0; mt < 4; ++mt) {
#pragma unroll
        for (int rr = 0; rr < 2; ++rr) {
            int m = bm + warp_m * 64 + mt * 16 + g + 8 * rr;
            size_t rowbase = ((size_t)bh * 512 + m) * 512;
#pragma unroll
            for (int nt = 0; nt < 4; ++nt) {
                int n = ncol[nt];
                float v0 = acc[mt][nt][2 * rr]     * mv0[nt] - (1.0f - mv0[nt]) * NEG;
                float v1 = acc[mt][nt][2 * rr + 1] * mv1[nt] - (1.0f - mv1[nt]) * NEG;
                if (m > n)     v0 -= NEG;
                if (m > n + 1) v1 -= NEG;
                __stcs((float2*)&out[rowbase + n],
                       make_float2(v0 * 0.125f, v1 * 0.125f));
            }
        }
    }
}

extern "C" void kernel_launch(void* const* d_in, const int* in_sizes, int n_in,
                              void* d_out, int out_size) {
    const float* inputs = (const float*)d_in[0];   // [16,512,1024]
    const int*   mask   = (const int*)d_in[1];     // [16,512]
    const float* W      = (const float*)d_in[2];   // [1024,1536]
    const float* bias   = (const float*)d_in[3];   // [1536]
    const float* pe     = (const float*)d_in[4];   // [512,64]
    float* out = (float*)d_out;                    // [16,12,512,512]

    (void)in_sizes; (void)n_in; (void)out_size;

    cudaFuncSetAttribute(proj_rope_fp8,
                         cudaFuncAttributeMaxDynamicSharedMemorySize, K1_SMEM);

    convertA8_kernel<<<4096, 256>>>(inputs);           // 8192*1024/8 threads
    wtrans8_kernel<<<dim3(48, 16), 256>>>(W);
    proj_rope_fp8<<<dim3(12, 64), 256, K1_SMEM>>>(bias, pe);
    qk_logits_kernel<<<dim3(4, 4, 192), 256>>>(mask, out);
}

// round 8
// speedup vs baseline: 1.1791x; 1.1791x over previous
#include <cuda_runtime.h>
#include <cuda_bf16.h>
#include <cuda_fp16.h>
#include <cstdint>

#define NEG 1000000000000.0f
#define WSCALE 32.0f
#define INV_WSCALE (1.0f / 32.0f)

// Pre-pass outputs.
__device__ uint8_t  g_A8[8192 * 1024];    // A e4m3 [8192][1024]
__device__ uint8_t  g_W8T[1536 * 1024];   // (32*W)^T e4m3 [1536][1024]
// Q/K after projection + RoPE: [bh][l][64] bf16 (bf16x2 words).
__device__ uint32_t g_Qh[192 * 512 * 32];
__device__ uint32_t g_Kh[192 * 512 * 32];

// ---------------------------------------------------------------------------
// helpers
// ---------------------------------------------------------------------------
__device__ __forceinline__ uint32_t pack_bf16x2(float lo, float hi) {
    uint32_t r;
    asm("cvt.rn.bf16x2.f32 %0, %1, %2;" : "=r"(r) : "f"(hi), "f"(lo));
    return r;
}

__device__ __forceinline__ uint32_t pack_e4m3x4(float v0, float v1, float v2, float v3) {
    uint32_t r;
    asm("{\n\t.reg .b16 l, h;\n\t"
        "cvt.rn.satfinite.e4m3x2.f32 l, %2, %1;\n\t"
        "cvt.rn.satfinite.e4m3x2.f32 h, %4, %3;\n\t"
        "mov.b32 %0, {l, h};\n\t}"
        : "=r"(r) : "f"(v0), "f"(v1), "f"(v2), "f"(v3));
    return r;
}

__device__ __forceinline__ uint32_t smem_u32(const void* p) {
    return (uint32_t)__cvta_generic_to_shared(p);
}

__device__ __forceinline__ void cp16(uint32_t dst, const void* src) {
    asm volatile("cp.async.cg.shared.global [%0], [%1], 16;" :: "r"(dst), "l"(src));
}
#define CP_COMMIT() asm volatile("cp.async.commit_group;" ::: "memory")
#define CP_WAIT1()  asm volatile("cp.async.wait_group 1;" ::: "memory")

#define SWZ128(x) ((x) ^ (((x) >> 3) & 0x70))

__device__ __forceinline__ void ldsm_x4(uint32_t& r0, uint32_t& r1,
                                        uint32_t& r2, uint32_t& r3, uint32_t addr) {
    asm volatile("ldmatrix.sync.aligned.m8n8.x4.shared.b16 {%0,%1,%2,%3}, [%4];"
                 : "=r"(r0), "=r"(r1), "=r"(r2), "=r"(r3) : "r"(addr));
}

// fp8 e4m3 mma with f16 accumulator: D[16x8] += A[16x32] * B[32x8]
__device__ __forceinline__ void mma_fp8_h(uint32_t* c, const uint32_t* a, const uint32_t* b) {
    asm volatile(
        "mma.sync.aligned.m16n8k32.row.col.f16.e4m3.e4m3.f16 "
        "{%0,%1}, {%2,%3,%4,%5}, {%6,%7}, {%0,%1};"
        : "+r"(c[0]), "+r"(c[1])
        : "r"(a[0]), "r"(a[1]), "r"(a[2]), "r"(a[3]), "r"(b[0]), "r"(b[1]));
}

// bf16 mma (fp32 acc) for kernel 2
__device__ __forceinline__ void mma_bf16(float* c, const uint32_t* a, const uint32_t* b) {
    asm volatile(
        "mma.sync.aligned.m16n8k16.row.col.f32.bf16.bf16.f32 "
        "{%0,%1,%2,%3}, {%4,%5,%6,%7}, {%8,%9}, {%0,%1,%2,%3};"
        : "+f"(c[0]), "+f"(c[1]), "+f"(c[2]), "+f"(c[3])
        : "r"(a[0]), "r"(a[1]), "r"(a[2]), "r"(a[3]), "r"(b[0]), "r"(b[1]));
}

// ---------------------------------------------------------------------------
// Pre-pass 1: A fp32 -> e4m3.
// ---------------------------------------------------------------------------
__global__ __launch_bounds__(256) void convertA8_kernel(const float* __restrict__ A) {
    size_t i = (size_t)blockIdx.x * 256 + threadIdx.x;   // < 8192*1024/8
    const float4* p = (const float4*)A + i * 2;
    float4 v0 = p[0], v1 = p[1];
    uint2 u;
    u.x = pack_e4m3x4(v0.x, v0.y, v0.z, v0.w);
    u.y = pack_e4m3x4(v1.x, v1.y, v1.z, v1.w);
    ((uint2*)g_A8)[i] = u;
}

// ---------------------------------------------------------------------------
// Pre-pass 2: W[1024,1536] fp32 -> (32*W)^T [1536,1024] e4m3.
// ---------------------------------------------------------------------------
__global__ __launch_bounds__(256) void wtrans8_kernel(const float* __restrict__ W) {
    __shared__ float s[64][33];
    const int tid = threadIdx.x;
    const int n0 = blockIdx.x * 32;
    const int k0 = blockIdx.y * 64;
#pragma unroll
    for (int r = 0; r < 8; ++r) {
        int idx = tid + r * 256;
        int kr = idx >> 5, nc = idx & 31;
        s[kr][nc] = W[(size_t)(k0 + kr) * 1536 + n0 + nc] * WSCALE;
    }
    __syncthreads();
    int n = tid >> 3;
    int kc = (tid & 7) * 8;
    uint2 u;
    u.x = pack_e4m3x4(s[kc + 0][n], s[kc + 1][n], s[kc + 2][n], s[kc + 3][n]);
    u.y = pack_e4m3x4(s[kc + 4][n], s[kc + 5][n], s[kc + 6][n], s[kc + 7][n]);
    *(uint2*)&g_W8T[(size_t)(n0 + n) * 1024 + k0 + kc] = u;
}

// ---------------------------------------------------------------------------
// Kernel 1: C = A @ W + b via fp8 mma.sync (f16 acc), fused RoPE -> bf16 Q/K.
// CTA: 128x128 (one head), BK=128 bytes, 3-stage cp.async, 256 threads.
// ---------------------------------------------------------------------------
#define STG8 32768
#define K1_SMEM (3 * STG8)

__global__ __launch_bounds__(256) void proj_rope_fp8(
    const float* __restrict__ bias,   // [1536]
    const float* __restrict__ pe)     // [512,64]
{
    extern __shared__ __align__(1024) char smem[];
    const uint32_t db = smem_u32(smem);

    const int tid = threadIdx.x;
    const int lane = tid & 31;
    const int wid = tid >> 5;
    const int warp_m = wid >> 2;
    const int warp_n = wid & 3;
    const int h  = blockIdx.x;
    const int bn = h * 128;
    const int bm = blockIdx.y * 128;

    uint32_t acc[4][4][2] = {};      // f16x2 accumulators

    const int a_row_l = warp_m * 64 + (lane & 15);
    const int a_kb_l  = (lane & 16);
    const int b_row_l = warp_n * 32 + (lane & 7) + ((lane >> 4) << 3);
    const int b_kb_l  = (lane & 8) << 1;

    auto issue_load = [&](int s, int k0) {
        const uint32_t ab = db + s * STG8;
#pragma unroll
        for (int r = 0; r < 4; ++r) {
            int idx = tid + r * 256;
            int row = idx >> 3, c = idx & 7;
            cp16(ab + SWZ128(row * 128 + c * 16),
                 g_A8 + (size_t)(bm + row) * 1024 + k0 + c * 16);
        }
        const uint32_t bb = ab + 16384;
#pragma unroll
        for (int r = 0; r < 4; ++r) {
            int idx = tid + r * 256;
            int row = idx >> 3, c = idx & 7;
            cp16(bb + SWZ128(row * 128 + c * 16),
                 g_W8T + (size_t)(bn + row) * 1024 + k0 + c * 16);
        }
        CP_COMMIT();
    };

    issue_load(0, 0);
    issue_load(1, 128);

    for (int it = 0; it < 8; ++it) {
        const int s = it - (it / 3) * 3;
        CP_WAIT1();
        __syncthreads();
        if (it + 2 < 8) {
            int s2 = (it + 2) - ((it + 2) / 3) * 3;
            issue_load(s2, (it + 2) * 128);
        } else {
            CP_COMMIT();
        }

        const uint32_t As_b = db + s * STG8;
        const uint32_t Bs_b = As_b + 16384;

#pragma unroll
        for (int ks = 0; ks < 4; ++ks) {
            const int kb = ks * 32;
            uint32_t af[4][4];
#pragma unroll
            for (int mt = 0; mt < 4; ++mt) {
                uint32_t addr = As_b + SWZ128((a_row_l + mt * 16) * 128 + kb + a_kb_l);
                ldsm_x4(af[mt][0], af[mt][1], af[mt][2], af[mt][3], addr);
            }
            uint32_t bf[4][2];
#pragma unroll
            for (int np = 0; np < 2; ++np) {
                uint32_t addr = Bs_b + SWZ128((b_row_l + np * 16) * 128 + kb + b_kb_l);
                ldsm_x4(bf[2 * np][0], bf[2 * np][1],
                        bf[2 * np + 1][0], bf[2 * np + 1][1], addr);
            }
#pragma unroll
            for (int mt = 0; mt < 4; ++mt)
#pragma unroll
                for (int nt = 0; nt < 4; ++nt)
                    mma_fp8_h(acc[mt][nt], af[mt], bf[nt]);
        }
        __syncthreads();
    }

    // ---- epilogue: 1/32 scale + bias + RoPE -> bf16 Q/K
    const int g = lane >> 2, t = lane & 3;
    const int cb = warp_n * 32;
    const bool isK = (cb >= 64);
    uint32_t* dst = isK ? g_Kh : g_Qh;

    float be[4], bo[4];
    int pi[4];
#pragma unroll
    for (int nt = 0; nt < 4; ++nt) {
        int c = cb + nt * 8 + 2 * t;
        be[nt] = bias[bn + c];
        bo[nt] = bias[bn + c + 1];
        pi[nt] = (c & 63) >> 1;
    }

    const float2* pe2 = (const float2*)pe;

#pragma unroll
    for (int mt = 0; mt < 4; ++mt) {
#pragma unroll
        for (int rr = 0; rr < 2; ++rr) {
            int m = bm + warp_m * 64 + mt * 16 + g + 8 * rr;
            int l = m & 511;
            int b = m >> 9;
            size_t rowb = ((size_t)(b * 12 + h) * 512 + l) * 32;
#pragma unroll
            for (int nt = 0; nt < 4; ++nt) {
                float2 sc = pe2[l * 32 + pi[nt]];   // x=sin, y=cos
                uint32_t ar = acc[mt][nt][rr];
                float2 f = __half22float2(*(half2*)&ar);
                float e = f.x * INV_WSCALE + be[nt];
                float o = f.y * INV_WSCALE + bo[nt];
                float re = e * sc.y - o * sc.x;
                float ro = o * sc.y + e * sc.x;
                dst[rowb + pi[nt]] = pack_bf16x2(re, ro);
            }
        }
    }
}

// ---------------------------------------------------------------------------
// Kernel 2: per (b,h): logits = Q @ K^T (bf16 mma.sync), fused mask/tril/scale.
// Strictly-below-diagonal tiles (by > bx) skip the GEMM entirely: every
// element there gets -NEG, so the qk term (|qk|~8 vs 1.25e11) is dropped.
// ---------------------------------------------------------------------------
#define PQ 72

__global__ __launch_bounds__(256) void qk_logits_kernel(
    const int* __restrict__ mask,   // [16,512]
    float* __restrict__ out)        // [16,12,512,512]
{
    __shared__ __align__(16) uint16_t Qs[128 * PQ];
    __shared__ __align__(16) uint16_t Ks[128 * PQ];

    const int tid = threadIdx.x;
    const int lane = tid & 31;
    const int wid = tid >> 5;
    const int warp_m = wid >> 2;
    const int warp_n = wid & 3;
    const int bh = blockIdx.z;
    const int b  = bh / 12;
    const int bm = blockIdx.y * 128;
    const int bn = blockIdx.x * 128;
    const bool skip = (blockIdx.y > blockIdx.x);   // all m > n in tile

    float acc[4][4][4] = {};

    if (!skip) {
        const uint4* Qg = (const uint4*)(g_Qh + ((size_t)bh * 512 + bm) * 32);
        const uint4* Kg = (const uint4*)(g_Kh + ((size_t)bh * 512 + bn) * 32);
#pragma unroll
        for (int r = 0; r < 4; ++r) {
            int chunk = tid + r * 256;
            int row = chunk >> 3;
            int kg  = chunk & 7;
            *(uint4*)&Qs[row * PQ + kg * 8] = Qg[row * 8 + kg];
            *(uint4*)&Ks[row * PQ + kg * 8] = Kg[row * 8 + kg];
        }
        __syncthreads();

        const uint32_t Qs_b = smem_u32(Qs);
        const uint32_t Ks_b = smem_u32(Ks);

        const int a_row_l = warp_m * 64 + (lane & 15);
        const int a_col_l = (lane & 16) ? 8 : 0;
        const int b_row_l = warp_n * 32 + (lane & 7) + ((lane & 16) >> 1);
        const int b_col_l = (lane & 8) ? 8 : 0;

#pragma unroll
        for (int ks = 0; ks < 4; ++ks) {
            int k = ks * 16;
            uint32_t af[4][4];
#pragma unroll
            for (int mt = 0; mt < 4; ++mt) {
                uint32_t addr = Qs_b + ((a_row_l + mt * 16) * PQ + k + a_col_l) * 2;
                ldsm_x4(af[mt][0], af[mt][1], af[mt][2], af[mt][3], addr);
            }
            uint32_t bf[4][2];
#pragma unroll
            for (int np = 0; np < 2; ++np) {
                uint32_t addr = Ks_b + ((b_row_l + np * 16) * PQ + k + b_col_l) * 2;
                ldsm_x4(bf[2 * np][0], bf[2 * np][1],
                        bf[2 * np + 1][0], bf[2 * np + 1][1], addr);
            }
#pragma unroll
            for (int mt = 0; mt < 4; ++mt)
#pragma unroll
                for (int nt = 0; nt < 4; ++nt)
                    mma_bf16(acc[mt][nt], af[mt], bf[nt]);
        }
    }

    const int g = lane >> 2, t = lane & 3;
    const int* mb = mask + b * 512;
    float mv0[4], mv1[4];
    int ncol[4];
#pragma unroll
    for (int nt = 0; nt < 4; ++nt) {
        int n = bn + warp_n * 32 + nt * 8 + 2 * t;
        ncol[nt] = n;
        mv0[nt] = (float)mb[n];
        mv1[nt] = (float)mb[n + 1];
    }

#pragma unroll
    for (int mt = 0; mt < 4; ++mt) {
#pragma unroll
        for (int rr = 0; rr < 2; ++rr) {
            int m = bm + warp_m * 64 + mt * 16 + g + 8 * rr;
            size_t rowbase = ((size_t)bh * 512 + m) * 512;
#pragma unroll
            for (int nt = 0; nt < 4; ++nt) {
                int n = ncol[nt];
                float v0 = acc[mt][nt][2 * rr]     * mv0[nt] - (1.0f - mv0[nt]) * NEG;
                float v1 = acc[mt][nt][2 * rr + 1] * mv1[nt] - (1.0f - mv1[nt]) * NEG;
                if (m > n)     v0 -= NEG;
                if (m > n + 1) v1 -= NEG;
                __stcs((float2*)&out[rowbase + n],
                       make_float2(v0 * 0.125f, v1 * 0.125f));
            }
        }
    }
}

extern "C" void kernel_launch(void* const* d_in, const int* in_sizes, int n_in,
                              void* d_out, int out_size) {
    const float* inputs = (const float*)d_in[0];   // [16,512,1024]
    const int*   mask   = (const int*)d_in[1];     // [16,512]
    const float* W      = (const float*)d_in[2];   // [1024,1536]
    const float* bias   = (const float*)d_in[3];   // [1536]
    const float* pe     = (const float*)d_in[4];   // [512,64]
    float* out = (float*)d_out;                    // [16,12,512,512]

    (void)in_sizes; (void)n_in; (void)out_size;

    cudaFuncSetAttribute(proj_rope_fp8,
                         cudaFuncAttributeMaxDynamicSharedMemorySize, K1_SMEM);

    convertA8_kernel<<<4096, 256>>>(inputs);
    wtrans8_kernel<<<dim3(48, 16), 256>>>(W);
    proj_rope_fp8<<<dim3(12, 64), 256, K1_SMEM>>>(bias, pe);
    qk_logits_kernel<<<dim3(4, 4, 192), 256>>>(mask, out);
}

// round 9
// speedup vs baseline: 1.2161x; 1.0314x over previous
#include <cuda_runtime.h>
#include <cuda_bf16.h>
#include <cuda_fp16.h>
#include <cstdint>

#define NEG8 125000000000.0f          // NEG / 8
#define WSCALE 32.0f
#define INV_WSCALE (1.0f / 32.0f)
#define QSCALE 16.0f
// logits = acc/(QSCALE^2) / 8
#define K2SCL (0.125f / 256.0f)

// Pre-pass outputs.
__device__ uint8_t g_A8[8192 * 1024];    // A e4m3 [8192][1024]
__device__ uint8_t g_W8T[1536 * 1024];   // (32*W)^T e4m3 [1536][1024]
// Q/K after projection + RoPE: [bh][l][64] e4m3 (x16 scale). 6.3 MB each.
__device__ uint8_t g_Q8[192 * 512 * 64];
__device__ uint8_t g_K8[192 * 512 * 64];

// ---------------------------------------------------------------------------
// helpers
// ---------------------------------------------------------------------------
__device__ __forceinline__ uint32_t pack_e4m3x4(float v0, float v1, float v2, float v3) {
    uint32_t r;
    asm("{\n\t.reg .b16 l, h;\n\t"
        "cvt.rn.satfinite.e4m3x2.f32 l, %2, %1;\n\t"
        "cvt.rn.satfinite.e4m3x2.f32 h, %4, %3;\n\t"
        "mov.b32 %0, {l, h};\n\t}"
        : "=r"(r) : "f"(v0), "f"(v1), "f"(v2), "f"(v3));
    return r;
}

__device__ __forceinline__ uint16_t pack_e4m3x2(float lo, float hi) {
    uint16_t r;
    asm("cvt.rn.satfinite.e4m3x2.f32 %0, %2, %1;" : "=h"(r) : "f"(lo), "f"(hi));
    return r;
}

__device__ __forceinline__ uint32_t smem_u32(const void* p) {
    return (uint32_t)__cvta_generic_to_shared(p);
}

__device__ __forceinline__ void cp16(uint32_t dst, const void* src) {
    asm volatile("cp.async.cg.shared.global [%0], [%1], 16;" :: "r"(dst), "l"(src));
}
#define CP_COMMIT() asm volatile("cp.async.commit_group;" ::: "memory")
#define CP_WAIT1()  asm volatile("cp.async.wait_group 1;" ::: "memory")

#define SWZ128(x) ((x) ^ (((x) >> 3) & 0x70))

__device__ __forceinline__ void ldsm_x4(uint32_t& r0, uint32_t& r1,
                                        uint32_t& r2, uint32_t& r3, uint32_t addr) {
    asm volatile("ldmatrix.sync.aligned.m8n8.x4.shared.b16 {%0,%1,%2,%3}, [%4];"
                 : "=r"(r0), "=r"(r1), "=r"(r2), "=r"(r3) : "r"(addr));
}

// fp8 e4m3 mma with f16 accumulator: D[16x8] += A[16x32] * B[32x8]
__device__ __forceinline__ void mma_fp8_h(uint32_t* c, const uint32_t* a, const uint32_t* b) {
    asm volatile(
        "mma.sync.aligned.m16n8k32.row.col.f16.e4m3.e4m3.f16 "
        "{%0,%1}, {%2,%3,%4,%5}, {%6,%7}, {%0,%1};"
        : "+r"(c[0]), "+r"(c[1])
        : "r"(a[0]), "r"(a[1]), "r"(a[2]), "r"(a[3]), "r"(b[0]), "r"(b[1]));
}

// ---------------------------------------------------------------------------
// Pre-pass 1: A fp32 -> e4m3.
// ---------------------------------------------------------------------------
__global__ __launch_bounds__(256) void convertA8_kernel(const float* __restrict__ A) {
    size_t i = (size_t)blockIdx.x * 256 + threadIdx.x;   // < 8192*1024/8
    const float4* p = (const float4*)A + i * 2;
    float4 v0 = p[0], v1 = p[1];
    uint2 u;
    u.x = pack_e4m3x4(v0.x, v0.y, v0.z, v0.w);
    u.y = pack_e4m3x4(v1.x, v1.y, v1.z, v1.w);
    ((uint2*)g_A8)[i] = u;
}

// ---------------------------------------------------------------------------
// Pre-pass 2: W[1024,1536] fp32 -> (32*W)^T [1536,1024] e4m3.
// ---------------------------------------------------------------------------
__global__ __launch_bounds__(256) void wtrans8_kernel(const float* __restrict__ W) {
    __shared__ float s[64][33];
    const int tid = threadIdx.x;
    const int n0 = blockIdx.x * 32;
    const int k0 = blockIdx.y * 64;
#pragma unroll
    for (int r = 0; r < 8; ++r) {
        int idx = tid + r * 256;
        int kr = idx >> 5, nc = idx & 31;
        s[kr][nc] = W[(size_t)(k0 + kr) * 1536 + n0 + nc] * WSCALE;
    }
    __syncthreads();
    int n = tid >> 3;
    int kc = (tid & 7) * 8;
    uint2 u;
    u.x = pack_e4m3x4(s[kc + 0][n], s[kc + 1][n], s[kc + 2][n], s[kc + 3][n]);
    u.y = pack_e4m3x4(s[kc + 4][n], s[kc + 5][n], s[kc + 6][n], s[kc + 7][n]);
    *(uint2*)&g_W8T[(size_t)(n0 + n) * 1024 + k0 + kc] = u;
}

// ---------------------------------------------------------------------------
// Kernel 1: C = A @ W + b via fp8 mma.sync (f16 acc), fused RoPE -> e4m3 Q/K.
// CTA: 128x128 (one head), BK=128 bytes, 3-stage cp.async, 256 threads.
// ---------------------------------------------------------------------------
#define STG8 32768
#define K1_SMEM (3 * STG8)

__global__ __launch_bounds__(256, 2) void proj_rope_fp8(
    const float* __restrict__ bias,   // [1536]
    const float* __restrict__ pe)     // [512,64]
{
    extern __shared__ __align__(1024) char smem[];
    const uint32_t db = smem_u32(smem);

    const int tid = threadIdx.x;
    const int lane = tid & 31;
    const int wid = tid >> 5;
    const int warp_m = wid >> 2;
    const int warp_n = wid & 3;
    const int h  = blockIdx.x;
    const int bn = h * 128;
    const int bm = blockIdx.y * 128;

    uint32_t acc[4][4][2] = {};      // f16x2 accumulators

    const int a_row_l = warp_m * 64 + (lane & 15);
    const int a_kb_l  = (lane & 16);
    const int b_row_l = warp_n * 32 + (lane & 7) + ((lane >> 4) << 3);
    const int b_kb_l  = (lane & 8) << 1;

    auto issue_load = [&](int s, int k0) {
        const uint32_t ab = db + s * STG8;
#pragma unroll
        for (int r = 0; r < 4; ++r) {
            int idx = tid + r * 256;
            int row = idx >> 3, c = idx & 7;
            cp16(ab + SWZ128(row * 128 + c * 16),
                 g_A8 + (size_t)(bm + row) * 1024 + k0 + c * 16);
        }
        const uint32_t bb = ab + 16384;
#pragma unroll
        for (int r = 0; r < 4; ++r) {
            int idx = tid + r * 256;
            int row = idx >> 3, c = idx & 7;
            cp16(bb + SWZ128(row * 128 + c * 16),
                 g_W8T + (size_t)(bn + row) * 1024 + k0 + c * 16);
        }
        CP_COMMIT();
    };

    issue_load(0, 0);
    issue_load(1, 128);

    for (int it = 0; it < 8; ++it) {
        const int s = it - (it / 3) * 3;
        CP_WAIT1();
        __syncthreads();
        if (it + 2 < 8) {
            int s2 = (it + 2) - ((it + 2) / 3) * 3;
            issue_load(s2, (it + 2) * 128);
        } else {
            CP_COMMIT();
        }

        const uint32_t As_b = db + s * STG8;
        const uint32_t Bs_b = As_b + 16384;

#pragma unroll
        for (int ks = 0; ks < 4; ++ks) {
            const int kb = ks * 32;
            uint32_t af[4][4];
#pragma unroll
            for (int mt = 0; mt < 4; ++mt) {
                uint32_t addr = As_b + SWZ128((a_row_l + mt * 16) * 128 + kb + a_kb_l);
                ldsm_x4(af[mt][0], af[mt][1], af[mt][2], af[mt][3], addr);
            }
            uint32_t bf[4][2];
#pragma unroll
            for (int np = 0; np < 2; ++np) {
                uint32_t addr = Bs_b + SWZ128((b_row_l + np * 16) * 128 + kb + b_kb_l);
                ldsm_x4(bf[2 * np][0], bf[2 * np][1],
                        bf[2 * np + 1][0], bf[2 * np + 1][1], addr);
            }
#pragma unroll
            for (int mt = 0; mt < 4; ++mt)
#pragma unroll
                for (int nt = 0; nt < 4; ++nt)
                    mma_fp8_h(acc[mt][nt], af[mt], bf[nt]);
        }
        // no trailing barrier: stage (it+2)%3 was last read in iter it-1,
        // and every warp is already past this iter's top barrier.
    }

    // ---- epilogue: 1/32 scale + bias + RoPE -> e4m3 (x16) Q/K
    const int g = lane >> 2, t = lane & 3;
    const int cb = warp_n * 32;
    const bool isK = (cb >= 64);
    uint16_t* dst = isK ? (uint16_t*)g_K8 : (uint16_t*)g_Q8;

    float be[4], bo[4];
    int pi[4];
#pragma unroll
    for (int nt = 0; nt < 4; ++nt) {
        int c = cb + nt * 8 + 2 * t;
        be[nt] = bias[bn + c];
        bo[nt] = bias[bn + c + 1];
        pi[nt] = (c & 63) >> 1;
    }

    const float2* pe2 = (const float2*)pe;

#pragma unroll
    for (int mt = 0; mt < 4; ++mt) {
#pragma unroll
        for (int rr = 0; rr < 2; ++rr) {
            int m = bm + warp_m * 64 + mt * 16 + g + 8 * rr;
            int l = m & 511;
            int b = m >> 9;
            size_t rowb = ((size_t)(b * 12 + h) * 512 + l) * 32;  // uint16 units
#pragma unroll
            for (int nt = 0; nt < 4; ++nt) {
                float2 sc = pe2[l * 32 + pi[nt]];   // x=sin, y=cos
                uint32_t ar = acc[mt][nt][rr];
                float2 f = __half22float2(*(half2*)&ar);
                float e = f.x * INV_WSCALE + be[nt];
                float o = f.y * INV_WSCALE + bo[nt];
                float re = (e * sc.y - o * sc.x) * QSCALE;
                float ro = (o * sc.y + e * sc.x) * QSCALE;
                dst[rowb + pi[nt]] = pack_e4m3x2(re, ro);
            }
        }
    }
}

// ---------------------------------------------------------------------------
// Kernel 2: per (b,h): logits = Q @ K^T via fp8 mma (f16 acc), fused
// mask/tril/scale. Tiles strictly below the diagonal skip the GEMM.
// CTA: 128x128, K=64 bytes resident, 256 threads (2m x 4n warps).
// ---------------------------------------------------------------------------
#define P8 80   // smem row pitch (bytes): conflict-free 8-row ldmatrix phases

__global__ __launch_bounds__(256) void qk_logits_fp8(
    const int* __restrict__ mask,   // [16,512]
    float* __restrict__ out)        // [16,12,512,512]
{
    __shared__ __align__(16) uint8_t Qs[128 * P8];
    __shared__ __align__(16) uint8_t Ks[128 * P8];

    const int tid = threadIdx.x;
    const int lane = tid & 31;
    const int wid = tid >> 5;
    const int warp_m = wid >> 2;
    const int warp_n = wid & 3;
    const int bh = blockIdx.z;
    const int b  = bh / 12;
    const int bm = blockIdx.y * 128;
    const int bn = blockIdx.x * 128;
    const bool skip = (blockIdx.y > blockIdx.x);

    uint32_t acc[4][4][2] = {};      // f16x2

    if (!skip) {
        const uint4* Qg = (const uint4*)(g_Q8 + ((size_t)bh * 512 + bm) * 64);
        const uint4* Kg = (const uint4*)(g_K8 + ((size_t)bh * 512 + bn) * 64);
#pragma unroll
        for (int r = 0; r < 2; ++r) {
            int idx = tid + r * 256;       // 512 chunks of 16B per tensor
            int row = idx >> 2, c = idx & 3;
            *(uint4*)&Qs[row * P8 + c * 16] = Qg[idx];
            *(uint4*)&Ks[row * P8 + c * 16] = Kg[idx];
        }
        __syncthreads();

        const uint32_t Qs_b = smem_u32(Qs);
        const uint32_t Ks_b = smem_u32(Ks);

        const int a_row_l = warp_m * 64 + (lane & 15);
        const int a_kb_l  = (lane & 16);
        const int b_row_l = warp_n * 32 + (lane & 7) + ((lane >> 4) << 3);
        const int b_kb_l  = (lane & 8) << 1;

#pragma unroll
        for (int ks = 0; ks < 2; ++ks) {
            const int kb = ks * 32;
            uint32_t af[4][4];
#pragma unroll
            for (int mt = 0; mt < 4; ++mt) {
                uint32_t addr = Qs_b + (a_row_l + mt * 16) * P8 + kb + a_kb_l;
                ldsm_x4(af[mt][0], af[mt][1], af[mt][2], af[mt][3], addr);
            }
            uint32_t bf[4][2];
#pragma unroll
            for (int np = 0; np < 2; ++np) {
                uint32_t addr = Ks_b + (b_row_l + np * 16) * P8 + kb + b_kb_l;
                ldsm_x4(bf[2 * np][0], bf[2 * np][1],
                        bf[2 * np + 1][0], bf[2 * np + 1][1], addr);
            }
#pragma unroll
            for (int mt = 0; mt < 4; ++mt)
#pragma unroll
                for (int nt = 0; nt < 4; ++nt)
                    mma_fp8_h(acc[mt][nt], af[mt], bf[nt]);
        }
    }

    // ---- epilogue: scale (folded 1/256 * 1/8), mask, strict lower-tri
    const int g = lane >> 2, t = lane & 3;
    const int* mb = mask + b * 512;
    float mv0[4], mv1[4];
    int ncol[4];
#pragma unroll
    for (int nt = 0; nt < 4; ++nt) {
        int n = bn + warp_n * 32 + nt * 8 + 2 * t;
        ncol[nt] = n;
        mv0[nt] = (float)mb[n];
        mv1[nt] = (float)mb[n + 1];
    }

#pragma unroll
    for (int mt = 0; mt < 4; ++mt) {
#pragma unroll
        for (int rr = 0; rr < 2; ++rr) {
            int m = bm + warp_m * 64 + mt * 16 + g + 8 * rr;
            size_t rowbase = ((size_t)bh * 512 + m) * 512;
#pragma unroll
            for (int nt = 0; nt < 4; ++nt) {
                int n = ncol[nt];
                uint32_t ar = acc[mt][nt][rr];
                float2 f = __half22float2(*(half2*)&ar);
                float v0 = f.x * K2SCL * mv0[nt] - (1.0f - mv0[nt]) * NEG8;
                float v1 = f.y * K2SCL * mv1[nt] - (1.0f - mv1[nt]) * NEG8;
                if (m > n)     v0 -= NEG8;
                if (m > n + 1) v1 -= NEG8;
                __stcs((float2*)&out[rowbase + n], make_float2(v0, v1));
            }
        }
    }
}

extern "C" void kernel_launch(void* const* d_in, const int* in_sizes, int n_in,
                              void* d_out, int out_size) {
    const float* inputs = (const float*)d_in[0];   // [16,512,1024]
    const int*   mask   = (const int*)d_in[1];     // [16,512]
    const float* W      = (const float*)d_in[2];   // [1024,1536]
    const float* bias   = (const float*)d_in[3];   // [1536]
    const float* pe     = (const float*)d_in[4];   // [512,64]
    float* out = (float*)d_out;                    // [16,12,512,512]

    (void)in_sizes; (void)n_in; (void)out_size;

    cudaFuncSetAttribute(proj_rope_fp8,
                         cudaFuncAttributeMaxDynamicSharedMemorySize, K1_SMEM);

    convertA8_kernel<<<4096, 256>>>(inputs);
    wtrans8_kernel<<<dim3(48, 16), 256>>>(W);
    proj_rope_fp8<<<dim3(12, 64), 256, K1_SMEM>>>(bias, pe);
    qk_logits_fp8<<<dim3(4, 4, 192), 256>>>(mask, out);
}